// round 1
// baseline (speedup 1.0000x reference)
#include <cuda_runtime.h>

// ce_loss_aux: masked binary cross-entropy over one-hot labels.
//   loss = -[ sum_{valid & y_true[...,1]==1} log(y_pred[...,1])
//           + sum_{valid & y_true[...,0]==1} log(y_pred[...,0]) ] / sum(doc_len)
// valid(b,l) = l < doc_len[b]
//
// Two-pass deterministic reduction:
//   kernel 1: grid-stride over pair-index space (2 positions / iter via float4
//             loads), per-block partial sums -> g_partials[]
//   kernel 2: single block reduces partials + doc_len, writes scalar.

#define NBLOCKS   1184          // 148 SMs * 8
#define NTHREADS  256
#define MAX_PARTIALS 2048

__device__ float g_partials[MAX_PARTIALS];

__global__ __launch_bounds__(NTHREADS)
void ce_partial_kernel(const float* __restrict__ y_true,
                       const float* __restrict__ y_pred,
                       const int*   __restrict__ doc_len,
                       int B, int L)
{
    const int pairsPerRow = L >> 1;                       // L is even (8192)
    const long long totalPairs = (long long)B * pairsPerRow;
    const long long stride = (long long)gridDim.x * blockDim.x;

    float acc = 0.0f;

    for (long long idx = (long long)blockIdx.x * blockDim.x + threadIdx.x;
         idx < totalPairs; idx += stride)
    {
        int b  = (int)(idx / pairsPerRow);
        int pr = (int)(idx - (long long)b * pairsPerRow);
        int l0 = pr << 1;

        int d = __ldg(&doc_len[b]);                       // 2KB, stays in L1
        if (l0 >= d) continue;                            // skip invalid -> no HBM read

        size_t off = ((size_t)b * L + (size_t)l0) * 2;    // multiple of 4 -> 16B aligned
        float4 t = *reinterpret_cast<const float4*>(y_true + off);
        float4 p = *reinterpret_cast<const float4*>(y_pred + off);

        // position l0: (ch0, ch1) = (t.x, t.y) / (p.x, p.y)
        float s = 0.0f;
        if (t.y == 1.0f) s -= logf(p.y);
        if (t.x == 1.0f) s -= logf(p.x);
        // position l0+1 (valid iff l0+1 < d): (t.z, t.w) / (p.z, p.w)
        if (l0 + 1 < d) {
            if (t.w == 1.0f) s -= logf(p.w);
            if (t.z == 1.0f) s -= logf(p.z);
        }
        acc += s;
    }

    // block reduction
    __shared__ float red[NTHREADS];
    red[threadIdx.x] = acc;
    __syncthreads();
    #pragma unroll
    for (int s = NTHREADS >> 1; s > 32; s >>= 1) {
        if (threadIdx.x < s) red[threadIdx.x] += red[threadIdx.x + s];
        __syncthreads();
    }
    if (threadIdx.x < 32) {
        float v = red[threadIdx.x] + red[threadIdx.x + 32];
        #pragma unroll
        for (int o = 16; o > 0; o >>= 1)
            v += __shfl_down_sync(0xFFFFFFFFu, v, o);
        if (threadIdx.x == 0) g_partials[blockIdx.x] = v;
    }
}

__global__ __launch_bounds__(1024)
void ce_final_kernel(const int* __restrict__ doc_len, int B, int nPartials,
                     float* __restrict__ out)
{
    __shared__ float sLoss[1024];
    __shared__ int   sLen[1024];

    float ls = 0.0f;
    for (int i = threadIdx.x; i < nPartials; i += blockDim.x)
        ls += g_partials[i];
    int ln = 0;
    for (int i = threadIdx.x; i < B; i += blockDim.x)
        ln += doc_len[i];

    sLoss[threadIdx.x] = ls;
    sLen[threadIdx.x]  = ln;
    __syncthreads();
    #pragma unroll
    for (int s = 512; s > 0; s >>= 1) {
        if (threadIdx.x < s) {
            sLoss[threadIdx.x] += sLoss[threadIdx.x + s];
            sLen[threadIdx.x]  += sLen[threadIdx.x + s];
        }
        __syncthreads();
    }
    if (threadIdx.x == 0)
        out[0] = sLoss[0] / (float)sLen[0];
}

extern "C" void kernel_launch(void* const* d_in, const int* in_sizes, int n_in,
                              void* d_out, int out_size)
{
    const float* y_true  = (const float*)d_in[0];
    const float* y_pred  = (const float*)d_in[1];
    const int*   doc_len = (const int*)d_in[2];
    float*       out     = (float*)d_out;

    int B = in_sizes[2];
    int L = in_sizes[0] / (2 * B);

    ce_partial_kernel<<<NBLOCKS, NTHREADS>>>(y_true, y_pred, doc_len, B, L);
    ce_final_kernel<<<1, 1024>>>(doc_len, B, NBLOCKS, out);
}

// round 2
// speedup vs baseline: 1.6617x; 1.6617x over previous
#include <cuda_runtime.h>

// ce_loss_aux: masked binary one-hot cross-entropy, fully fused single kernel.
//
// Grid: one block per (row, chunk) where chunk = 1024 pairs (2048 positions).
//   - chunk entirely beyond doc_len[b]  -> zero loads, immediate partial=0
//   - chunk entirely valid              -> branch-free unrolled fast path (MLP 8)
//   - boundary chunk                    -> per-pair predication
// Final scalar produced by the last block to arrive (threadfence + counter),
// summing per-block partials in a fixed order -> deterministic.

#define NTHREADS 256
#define PAIRS_PER_THREAD 4
#define CHUNK_PAIRS (NTHREADS * PAIRS_PER_THREAD)   // 1024 pairs / block

__device__ float        g_partials[8192];
__device__ unsigned int g_counter;                  // zero-init; reset by last block

__global__ __launch_bounds__(NTHREADS)
void ce_fused_kernel(const float* __restrict__ y_true,
                     const float* __restrict__ y_pred,
                     const int*   __restrict__ doc_len,
                     float* __restrict__ out,
                     int B, int L, int chunksPerRow, int nBlocks)
{
    const int b     = blockIdx.x / chunksPerRow;
    const int chunk = blockIdx.x - b * chunksPerRow;
    const int d     = __ldg(&doc_len[b]);

    const int pairBase = chunk * CHUNK_PAIRS;       // first pair index in this chunk
    const int lStart   = pairBase * 2;

    float acc = 0.0f;

    if (lStart < d) {
        const float4* t4 = reinterpret_cast<const float4*>(y_true) + (size_t)b * (L >> 1);
        const float4* p4 = reinterpret_cast<const float4*>(y_pred) + (size_t)b * (L >> 1);
        const int lEnd = lStart + CHUNK_PAIRS * 2;

        if (lEnd <= d) {
            // fully valid: independent loads, no data-dependent branches
            #pragma unroll
            for (int i = 0; i < PAIRS_PER_THREAD; i++) {
                int pr = pairBase + i * NTHREADS + threadIdx.x;
                float4 t = __ldg(&t4[pr]);
                float4 p = __ldg(&p4[pr]);
                float s0 = (t.y == 1.0f) ? p.y : p.x;   // one-hot select
                float s1 = (t.w == 1.0f) ? p.w : p.z;
                acc -= __logf(s0) + __logf(s1);
            }
        } else {
            // boundary chunk: per-pair predication on d
            #pragma unroll
            for (int i = 0; i < PAIRS_PER_THREAD; i++) {
                int pr = pairBase + i * NTHREADS + threadIdx.x;
                int l0 = pr << 1;
                if (l0 < d) {
                    float4 t = __ldg(&t4[pr]);
                    float4 p = __ldg(&p4[pr]);
                    float s0 = (t.y == 1.0f) ? p.y : p.x;
                    acc -= __logf(s0);
                    if (l0 + 1 < d) {
                        float s1 = (t.w == 1.0f) ? p.w : p.z;
                        acc -= __logf(s1);
                    }
                }
            }
        }
    }

    // ---- block reduction ----
    __shared__ float red[NTHREADS / 32];
    #pragma unroll
    for (int o = 16; o > 0; o >>= 1)
        acc += __shfl_down_sync(0xFFFFFFFFu, acc, o);
    if ((threadIdx.x & 31) == 0) red[threadIdx.x >> 5] = acc;
    __syncthreads();
    if (threadIdx.x < 32) {
        float v = (threadIdx.x < NTHREADS / 32) ? red[threadIdx.x] : 0.0f;
        #pragma unroll
        for (int o = 4; o > 0; o >>= 1)
            v += __shfl_down_sync(0xFFFFFFFFu, v, o);
        if (threadIdx.x == 0) g_partials[blockIdx.x] = v;
    }

    // ---- last-block final reduction (deterministic fixed-order sums) ----
    __shared__ bool amLast;
    if (threadIdx.x == 0) {
        __threadfence();
        unsigned int prev = atomicAdd(&g_counter, 1u);
        amLast = (prev == (unsigned int)(nBlocks - 1));
    }
    __syncthreads();

    if (amLast) {
        float ls = 0.0f;
        for (int i = threadIdx.x; i < nBlocks; i += NTHREADS)
            ls += g_partials[i];
        float ln = 0.0f;
        for (int i = threadIdx.x; i < B; i += NTHREADS)
            ln += (float)__ldg(&doc_len[i]);

        #pragma unroll
        for (int o = 16; o > 0; o >>= 1) {
            ls += __shfl_down_sync(0xFFFFFFFFu, ls, o);
            ln += __shfl_down_sync(0xFFFFFFFFu, ln, o);
        }
        __shared__ float rl[NTHREADS / 32], rn[NTHREADS / 32];
        if ((threadIdx.x & 31) == 0) {
            rl[threadIdx.x >> 5] = ls;
            rn[threadIdx.x >> 5] = ln;
        }
        __syncthreads();
        if (threadIdx.x == 0) {
            float sumL = 0.0f, sumN = 0.0f;
            #pragma unroll
            for (int i = 0; i < NTHREADS / 32; i++) { sumL += rl[i]; sumN += rn[i]; }
            out[0] = sumL / sumN;
            g_counter = 0;                      // reset for next graph replay
        }
    }
}

extern "C" void kernel_launch(void* const* d_in, const int* in_sizes, int n_in,
                              void* d_out, int out_size)
{
    const float* y_true  = (const float*)d_in[0];
    const float* y_pred  = (const float*)d_in[1];
    const int*   doc_len = (const int*)d_in[2];
    float*       out     = (float*)d_out;

    int B = in_sizes[2];
    int L = in_sizes[0] / (2 * B);

    int pairsPerRow  = L >> 1;
    int chunksPerRow = (pairsPerRow + CHUNK_PAIRS - 1) / CHUNK_PAIRS;
    int nBlocks      = B * chunksPerRow;

    ce_fused_kernel<<<nBlocks, NTHREADS>>>(y_true, y_pred, doc_len, out,
                                           B, L, chunksPerRow, nBlocks);
}

// round 3
// speedup vs baseline: 1.9329x; 1.1633x over previous
#include <cuda_runtime.h>

// ce_loss_aux: masked binary one-hot cross-entropy, fused single kernel.
//
// Grid: one block per (row, chunk), chunk = 2048 pairs (4096 positions).
//   - chunk fully beyond doc_len[b] -> zero loads
//   - chunk fully valid             -> two-phase: 16 front-batched LDG.128,
//                                     then compute (MLP_p1 = 16)
//   - boundary chunk                -> per-pair predication
// Last-arriving block does the final deterministic reduction.

#define NTHREADS 256
#define PPT 8                                   // float4-pairs per thread
#define CHUNK_PAIRS (NTHREADS * PPT)            // 2048 pairs / block

__device__ float        g_partials[8192];
__device__ unsigned int g_counter;              // zero-init; reset by last block

__global__ __launch_bounds__(NTHREADS)
void ce_fused_kernel(const float* __restrict__ y_true,
                     const float* __restrict__ y_pred,
                     const int*   __restrict__ doc_len,
                     float* __restrict__ out,
                     int B, int L, int chunksPerRow, int nBlocks)
{
    const int b     = blockIdx.x / chunksPerRow;
    const int chunk = blockIdx.x - b * chunksPerRow;
    const int d     = __ldg(&doc_len[b]);

    const int pairBase = chunk * CHUNK_PAIRS;
    const int lStart   = pairBase * 2;

    float acc = 0.0f;

    if (lStart < d) {
        const float4* t4 = reinterpret_cast<const float4*>(y_true) + (size_t)b * (L >> 1);
        const float4* p4 = reinterpret_cast<const float4*>(y_pred) + (size_t)b * (L >> 1);
        const int lEnd = lStart + CHUNK_PAIRS * 2;

        if (lEnd <= d) {
            // ---- fully valid: front-batch ALL loads, then compute ----
            float4 t[PPT], p[PPT];
            #pragma unroll
            for (int i = 0; i < PPT; i++)
                t[i] = __ldg(&t4[pairBase + i * NTHREADS + threadIdx.x]);
            #pragma unroll
            for (int i = 0; i < PPT; i++)
                p[i] = __ldg(&p4[pairBase + i * NTHREADS + threadIdx.x]);

            #pragma unroll
            for (int i = 0; i < PPT; i++) {
                float s0 = (t[i].y == 1.0f) ? p[i].y : p[i].x;   // one-hot select
                float s1 = (t[i].w == 1.0f) ? p[i].w : p[i].z;
                acc -= __logf(s0 * s1);      // product in (1e-8, 1): safe in fp32
            }
        } else {
            // ---- boundary chunk: per-pair predication on d ----
            #pragma unroll
            for (int i = 0; i < PPT; i++) {
                int pr = pairBase + i * NTHREADS + threadIdx.x;
                int l0 = pr << 1;
                if (l0 < d) {
                    float4 t = __ldg(&t4[pr]);
                    float4 p = __ldg(&p4[pr]);
                    float s0 = (t.y == 1.0f) ? p.y : p.x;
                    acc -= __logf(s0);
                    if (l0 + 1 < d) {
                        float s1 = (t.w == 1.0f) ? p.w : p.z;
                        acc -= __logf(s1);
                    }
                }
            }
        }
    }

    // ---- block reduction ----
    __shared__ float red[NTHREADS / 32];
    #pragma unroll
    for (int o = 16; o > 0; o >>= 1)
        acc += __shfl_down_sync(0xFFFFFFFFu, acc, o);
    if ((threadIdx.x & 31) == 0) red[threadIdx.x >> 5] = acc;
    __syncthreads();
    if (threadIdx.x < 32) {
        float v = (threadIdx.x < NTHREADS / 32) ? red[threadIdx.x] : 0.0f;
        #pragma unroll
        for (int o = 4; o > 0; o >>= 1)
            v += __shfl_down_sync(0xFFFFFFFFu, v, o);
        if (threadIdx.x == 0) g_partials[blockIdx.x] = v;
    }

    // ---- last-block final reduction (deterministic fixed-order sums) ----
    __shared__ bool amLast;
    if (threadIdx.x == 0) {
        __threadfence();
        unsigned int prev = atomicAdd(&g_counter, 1u);
        amLast = (prev == (unsigned int)(nBlocks - 1));
    }
    __syncthreads();

    if (amLast) {
        float ls = 0.0f;
        for (int i = threadIdx.x; i < nBlocks; i += NTHREADS)
            ls += g_partials[i];
        float ln = 0.0f;
        for (int i = threadIdx.x; i < B; i += NTHREADS)
            ln += (float)__ldg(&doc_len[i]);

        #pragma unroll
        for (int o = 16; o > 0; o >>= 1) {
            ls += __shfl_down_sync(0xFFFFFFFFu, ls, o);
            ln += __shfl_down_sync(0xFFFFFFFFu, ln, o);
        }
        __shared__ float rl[NTHREADS / 32], rn[NTHREADS / 32];
        if ((threadIdx.x & 31) == 0) {
            rl[threadIdx.x >> 5] = ls;
            rn[threadIdx.x >> 5] = ln;
        }
        __syncthreads();
        if (threadIdx.x == 0) {
            float sumL = 0.0f, sumN = 0.0f;
            #pragma unroll
            for (int i = 0; i < NTHREADS / 32; i++) { sumL += rl[i]; sumN += rn[i]; }
            out[0] = sumL / sumN;
            g_counter = 0;                      // reset for next graph replay
        }
    }
}

extern "C" void kernel_launch(void* const* d_in, const int* in_sizes, int n_in,
                              void* d_out, int out_size)
{
    const float* y_true  = (const float*)d_in[0];
    const float* y_pred  = (const float*)d_in[1];
    const int*   doc_len = (const int*)d_in[2];
    float*       out     = (float*)d_out;

    int B = in_sizes[2];
    int L = in_sizes[0] / (2 * B);

    int pairsPerRow  = L >> 1;
    int chunksPerRow = (pairsPerRow + CHUNK_PAIRS - 1) / CHUNK_PAIRS;
    int nBlocks      = B * chunksPerRow;

    ce_fused_kernel<<<nBlocks, NTHREADS>>>(y_true, y_pred, doc_len, out,
                                           B, L, chunksPerRow, nBlocks);
}